// round 15
// baseline (speedup 1.0000x reference)
#include <cuda_runtime.h>
#include <math_constants.h>
#include <cstdint>

#define BB   4
#define NH   8
#define HD   32
#define QL   1024
#define KVL  4096
#define CC   256
#define NT   16129                       // (2*64-1)^2
#define QSCALE 0.17677669529663687f      // 32^-0.5

// Scratch (device globals: no allocation allowed)
__device__ float g_Qp[BB*NH*QL*HD];      // (bh, q, d)
__device__ float g_Kt[BB*NH*HD*KVL];     // (bh, d, k)  transposed for QK
__device__ float g_V [BB*NH*KVL*HD];     // (bh, k, d)  row-major for PV
__device__ float g_X [BB*QL*CC];         // (b, q, c)
__device__ float g_biasT[NH*NT];         // per-head transposed bias table

// ---------------------------------------------------------------------------
__global__ void bias_prep(const float* __restrict__ bt)
{
    int i = blockIdx.x * 256 + threadIdx.x;
    if (i < NH * NT) {
        int h = i / NT, idx = i - h * NT;
        g_biasT[i] = bt[idx * NH + h];
    }
}

// ---------------------------------------------------------------------------
// Tiled GEMM: out = A(MxK) @ W(NxK)^T + bias, 64x64 tile, 256 threads.
// mode 0: out-proj (A := g_X, row-major out)
// mode 1: q-proj   (scale + scatter to g_Qp (bh,q,d))
// mode 2: kv-proj  (K -> g_Kt transposed scatter, V -> g_V row-major float4)
// ---------------------------------------------------------------------------
__global__ void __launch_bounds__(256) gemm_kernel(
    const float* __restrict__ A, const float* __restrict__ W,
    const float* __restrict__ bias, float* __restrict__ out,
    int M, int N, int K, int mode)
{
    __shared__ float As[64*32];
    __shared__ float Ws[64*33];

    if (mode == 0) A = g_X;

    const int tid = threadIdx.x;
    const int ty = tid >> 4, tx = tid & 15;
    const int m0 = blockIdx.x * 64, n0 = blockIdx.y * 64;

    float s[4][4] = {};

    for (int kc = 0; kc < K; kc += 32) {
        {
            int f = tid * 8, r = f >> 5, k = f & 31;
            const float4* src = (const float4*)&A[(size_t)(m0 + r) * K + kc + k];
            *(float4*)&As[r*32 + k]     = src[0];
            *(float4*)&As[r*32 + k + 4] = src[1];
        }
        {
            int f = tid * 8, c = f >> 5, k = f & 31;
            const float4* src = (const float4*)&W[(size_t)(n0 + c) * K + kc + k];
            float4 v0 = src[0], v1 = src[1];
            float* d = &Ws[c*33 + k];
            d[0]=v0.x; d[1]=v0.y; d[2]=v0.z; d[3]=v0.w;
            d[4]=v1.x; d[5]=v1.y; d[6]=v1.z; d[7]=v1.w;
        }
        __syncthreads();

        #pragma unroll
        for (int k = 0; k < 32; k += 4) {
            float4 a[4];
            #pragma unroll
            for (int i = 0; i < 4; i++) a[i] = *(float4*)&As[(ty*4+i)*32 + k];
            #pragma unroll
            for (int j = 0; j < 4; j++) {
                const float* wp = &Ws[(tx*4+j)*33 + k];
                float w0 = wp[0], w1 = wp[1], w2 = wp[2], w3 = wp[3];
                #pragma unroll
                for (int i = 0; i < 4; i++)
                    s[i][j] += a[i].x*w0 + a[i].y*w1 + a[i].z*w2 + a[i].w*w3;
            }
        }
        __syncthreads();
    }

    const int cbase = n0 + tx*4;

    if (mode == 0) {
        float4 bb = *(const float4*)&bias[cbase];
        #pragma unroll
        for (int i = 0; i < 4; i++) {
            int m = m0 + ty*4 + i;
            *(float4*)&out[(size_t)m * N + cbase] =
                make_float4(s[i][0]+bb.x, s[i][1]+bb.y, s[i][2]+bb.z, s[i][3]+bb.w);
        }
    } else if (mode == 1) {
        float4 bb = *(const float4*)&bias[cbase];
        int h = cbase >> 5, d = cbase & 31;
        #pragma unroll
        for (int i = 0; i < 4; i++) {
            int m = m0 + ty*4 + i;
            int b = m >> 10, qi = m & 1023;
            *(float4*)&g_Qp[(size_t)((b*NH + h)*QL + qi)*HD + d] =
                make_float4((s[i][0]+bb.x)*QSCALE, (s[i][1]+bb.y)*QSCALE,
                            (s[i][2]+bb.z)*QSCALE, (s[i][3]+bb.w)*QSCALE);
        }
    } else {
        int sel = cbase >> 8;                   // uniform per block (n0 mult of 64)
        if (sel) {                              // V: (bh, k, d) float4 stores
            int h = (cbase >> 5) & 7, d = cbase & 31;
            float4 bb = *(const float4*)&bias[cbase];
            #pragma unroll
            for (int i = 0; i < 4; i++) {
                int m = m0 + ty*4 + i;
                int b = m >> 12, kk = m & 4095;
                *(float4*)&g_V[((size_t)(b*NH + h)*KVL + kk)*HD + d] =
                    make_float4(s[i][0]+bb.x, s[i][1]+bb.y, s[i][2]+bb.z, s[i][3]+bb.w);
            }
        } else {                                // K: (bh, d, k) transposed scatter
            #pragma unroll
            for (int j = 0; j < 4; j++) {
                int c = cbase + j;
                int h = (c >> 5) & 7, d = c & 31;
                float bv = bias[c];
                #pragma unroll
                for (int i = 0; i < 4; i++) {
                    int m = m0 + ty*4 + i;
                    int b = m >> 12, kk = m & 4095;
                    g_Kt[((size_t)(b*NH + h)*HD + d)*KVL + kk] = s[i][j] + bv;
                }
            }
        }
    }
}

// ---------------------------------------------------------------------------
// Fused attention. One CTA per (bh, 64-q-row tile). Online softmax.
// Analytic bias index (exact replication of the reference reshape):
//   row q, col = kt*64 + d :
//     c = kt & 31 (wz), p = kt >> 5 (hx parity)
//     zf = 528 + (q>>5)*32 + c ; zh = zf>>6 ; zw = zf&63
//     t = p*32 + d ; xh = (q&31) + (t>>6) ; xw = t&63
//     idx = (zh-xh+63)*127 + (zw-xw+63)
//   and for a thread's 4 consecutive cols: idx(j) = idx(0) - j.
// ---------------------------------------------------------------------------
__device__ __forceinline__ void cpa16(uint32_t dst, const float* src)
{
    asm volatile("cp.async.ca.shared.global [%0], [%1], 16;\n" :: "r"(dst), "l"(src));
}

#define SM_Q    0
#define SM_K    2048
#define SM_V    6144
#define SM_P    10752
#define SM_AL   14848
#define SM_LL   14912
#define SM_FLOATS 14976

__global__ void __launch_bounds__(256) attn_kernel()
{
    extern __shared__ float sm[];
    float* Qs  = sm + SM_Q;
    float* Kts = sm + SM_K;     // 2 x [32][64]
    float* Vkd = sm + SM_V;     // 2 x [64][36]
    float* Ps  = sm + SM_P;     // [64][64]
    float* Al  = sm + SM_AL;
    float* Ll  = sm + SM_LL;

    const int tid  = threadIdx.x;
    const int ty   = tid >> 4, tx = tid & 15;
    const int lane = tid & 31, w  = tid >> 5;
    const int bh   = blockIdx.y, b = bh >> 3, h = bh & 7;
    const int qt   = blockIdx.x;

    const uint32_t smbase = (uint32_t)__cvta_generic_to_shared(sm);

    // Q tile (read once, broadcast-consumed)
    {
        const float4* src = (const float4*)&g_Qp[((size_t)bh*QL + qt*64)*HD + tid*8];
        *(float4*)&Qs[tid*8]     = src[0];
        *(float4*)&Qs[tid*8 + 4] = src[1];
    }

    const float* bT = &g_biasT[h * NT];
    const size_t kbase = (size_t)bh * HD * KVL;
    const size_t vbase = (size_t)bh * KVL * HD;

    const int fk = tid*8, kd = fk >> 6, kj = fk & 63;
    const int vk = fk >> 5, vd = fk & 31;

    // preload tile 0
    {
        const float* ks = &g_Kt[kbase + (size_t)kd*KVL + kj];
        uint32_t kdst = smbase + (SM_K + kd*64 + kj)*4;
        cpa16(kdst, ks); cpa16(kdst+16, ks+4);
        const float* vs = &g_V[vbase + (size_t)vk*HD + vd];
        uint32_t vdst = smbase + (SM_V + vk*36 + vd)*4;
        cpa16(vdst, vs); cpa16(vdst+16, vs+4);
        asm volatile("cp.async.commit_group;\n");
    }

    float m[4], l[4], O[8];
    #pragma unroll
    for (int i = 0; i < 4; i++) { m[i] = -CUDART_INF_F; l[i] = 0.f; }
    #pragma unroll
    for (int r = 0; r < 8; r++) O[r] = 0.f;

    // per-row bias seed components (q rows this thread owns: qt*64+ty*4+i)
    //   zf_base(i) = 528 + (q>>5)*32   (c added per tile)
    //   xh_base(i) = q & 31
    int zfb[4], xhb[4];
    #pragma unroll
    for (int i = 0; i < 4; i++) {
        int q = qt*64 + ty*4 + i;
        zfb[i] = 528 + (q >> 5) * 32;
        xhb[i] = q & 31;
    }

    for (int kt = 0; kt < KVL/64; kt++) {
        const int buf = kt & 1;

        // ---- bias-initialized accumulators (LDGs issued before barrier) ----
        const int c = kt & 31, p = kt >> 5;
        const int t0 = p*32 + tx*4;
        const int tcar = t0 >> 6, xw0 = t0 & 63;
        float s[4][4];
        #pragma unroll
        for (int i = 0; i < 4; i++) {
            int zf = zfb[i] + c;
            int zh = zf >> 6, zw = zf & 63;
            int xh = xhb[i] + tcar;
            int idx0 = (zh - xh + 63)*127 + (zw - xw0 + 63);
            s[i][0] = __ldg(&bT[idx0    ]);
            s[i][1] = __ldg(&bT[idx0 - 1]);
            s[i][2] = __ldg(&bT[idx0 - 2]);
            s[i][3] = __ldg(&bT[idx0 - 3]);
        }

        asm volatile("cp.async.wait_group 0;\n");
        __syncthreads();   // tile visible; prev iter's PV done with other buffer

        if (kt < KVL/64 - 1) {   // prefetch next tile into other buffer
            const int nb = (kt+1) & 1;
            const int kbn = (kt+1)*64;
            const float* ks = &g_Kt[kbase + (size_t)kd*KVL + kbn + kj];
            uint32_t kdst = smbase + (SM_K + nb*2048 + kd*64 + kj)*4;
            cpa16(kdst, ks); cpa16(kdst+16, ks+4);
            const float* vs = &g_V[vbase + (size_t)(kbn + vk)*HD + vd];
            uint32_t vdst = smbase + (SM_V + nb*2304 + vk*36 + vd)*4;
            cpa16(vdst, vs); cpa16(vdst+16, vs+4);
            asm volatile("cp.async.commit_group;\n");
        }

        const float* K = &Kts[buf*2048];
        const float* V = &Vkd[buf*2304];

        // ---- S = QK^T + bias ----
        #pragma unroll
        for (int d4 = 0; d4 < 32; d4 += 4) {
            float4 k0 = *(const float4*)&K[(d4+0)*64 + tx*4];
            float4 k1 = *(const float4*)&K[(d4+1)*64 + tx*4];
            float4 k2 = *(const float4*)&K[(d4+2)*64 + tx*4];
            float4 k3 = *(const float4*)&K[(d4+3)*64 + tx*4];
            #pragma unroll
            for (int i = 0; i < 4; i++) {
                float4 q = *(const float4*)&Qs[(ty*4+i)*32 + d4];
                s[i][0] += q.x*k0.x + q.y*k1.x + q.z*k2.x + q.w*k3.x;
                s[i][1] += q.x*k0.y + q.y*k1.y + q.z*k2.y + q.w*k3.y;
                s[i][2] += q.x*k0.z + q.y*k1.z + q.z*k2.z + q.w*k3.z;
                s[i][3] += q.x*k0.w + q.y*k1.w + q.z*k2.w + q.w*k3.w;
            }
        }

        // ---- online softmax (warp-private rows) ----
        #pragma unroll
        for (int i = 0; i < 4; i++) {
            float mt = fmaxf(fmaxf(s[i][0], s[i][1]), fmaxf(s[i][2], s[i][3]));
            #pragma unroll
            for (int o = 8; o >= 1; o >>= 1)
                mt = fmaxf(mt, __shfl_xor_sync(0xffffffffu, mt, o));
            float mn    = fmaxf(m[i], mt);
            float alpha = __expf(m[i] - mn);
            m[i] = mn;
            float p0 = __expf(s[i][0]-mn), p1 = __expf(s[i][1]-mn);
            float p2 = __expf(s[i][2]-mn), p3 = __expf(s[i][3]-mn);
            float rs = p0 + p1 + p2 + p3;
            #pragma unroll
            for (int o = 8; o >= 1; o >>= 1)
                rs += __shfl_xor_sync(0xffffffffu, rs, o);
            l[i] = l[i]*alpha + rs;
            if (tx == 0) Al[ty*4 + i] = alpha;
            *(float4*)&Ps[(ty*4+i)*64 + tx*4] = make_float4(p0, p1, p2, p3);
        }
        __syncwarp();   // Ps/Al are warp-private

        // ---- O += P V : lane = d, warp owns its 8 rows ----
        float av[8];
        #pragma unroll
        for (int r = 0; r < 8; r++) av[r] = Al[w*8 + r];
        #pragma unroll
        for (int r = 0; r < 8; r++) O[r] *= av[r];

        #pragma unroll 4
        for (int k4 = 0; k4 < 64; k4 += 4) {
            float vx = V[(k4+0)*36 + lane];
            float vy = V[(k4+1)*36 + lane];
            float vz = V[(k4+2)*36 + lane];
            float vw = V[(k4+3)*36 + lane];
            #pragma unroll
            for (int r = 0; r < 8; r++) {
                float4 pr = *(const float4*)&Ps[(w*8+r)*64 + k4];
                O[r] += pr.x*vx + pr.y*vy + pr.z*vz + pr.w*vw;
            }
        }
    }

    // epilogue
    if (tx == 0) {
        #pragma unroll
        for (int i = 0; i < 4; i++) Ll[ty*4 + i] = l[i];
    }
    __syncwarp();
    #pragma unroll
    for (int r = 0; r < 8; r++) {
        int row = w*8 + r;
        float inv = 1.0f / Ll[row];
        int q = qt*64 + row;
        g_X[((size_t)b*QL + q)*CC + h*HD + lane] = O[r] * inv;
    }
}

// ---------------------------------------------------------------------------
extern "C" void kernel_launch(void* const* d_in, const int* in_sizes, int n_in,
                              void* d_out, int out_size)
{
    const float* q          = (const float*)d_in[0];
    const float* kv         = (const float*)d_in[1];
    const float* Wq         = (const float*)d_in[2];
    const float* bq         = (const float*)d_in[3];
    const float* Wkv        = (const float*)d_in[4];
    const float* bkv        = (const float*)d_in[5];
    const float* bias_table = (const float*)d_in[6];
    const float* Wp         = (const float*)d_in[7];
    const float* bp         = (const float*)d_in[8];
    float* out = (float*)d_out;

    cudaFuncSetAttribute(attn_kernel,
        cudaFuncAttributeMaxDynamicSharedMemorySize, SM_FLOATS * 4);

    dim3 blk(256);
    bias_prep<<<(NH*NT + 255)/256, blk>>>(bias_table);
    gemm_kernel<<<dim3(64, 4),  blk>>>(q,  Wq,  bq,  nullptr, BB*QL,  CC,   CC, 1);
    gemm_kernel<<<dim3(256, 8), blk>>>(kv, Wkv, bkv, nullptr, BB*KVL, 2*CC, CC, 2);
    attn_kernel<<<dim3(QL/64, BB*NH), blk, SM_FLOATS * 4>>>();
    gemm_kernel<<<dim3(64, 4),  blk>>>(nullptr, Wp, bp, out, BB*QL, CC, CC, 0);
}

// round 16
// speedup vs baseline: 1.0043x; 1.0043x over previous
#include <cuda_runtime.h>
#include <math_constants.h>
#include <cstdint>

#define BB   4
#define NH   8
#define HD   32
#define QL   1024
#define KVL  4096
#define CC   256
#define NT   16129                       // (2*64-1)^2
#define QSCALE 0.17677669529663687f      // 32^-0.5

// Scratch (device globals: no allocation allowed)
__device__ float g_Qp[BB*NH*QL*HD];      // (bh, q, d)
__device__ float g_Kt[BB*NH*HD*KVL];     // (bh, d, k)  transposed for QK
__device__ float g_V [BB*NH*KVL*HD];     // (bh, k, d)  row-major for PV
__device__ float g_X [BB*QL*CC];         // (b, q, c)
__device__ float g_biasT[NH*NT];         // per-head transposed bias table

// ---------------------------------------------------------------------------
__global__ void bias_prep(const float* __restrict__ bt)
{
    int i = blockIdx.x * 256 + threadIdx.x;
    if (i < NH * NT) {
        int h = i / NT, idx = i - h * NT;
        g_biasT[i] = bt[idx * NH + h];
    }
}

// ---------------------------------------------------------------------------
// Tiled GEMM: out = A(MxK) @ W(NxK)^T + bias, 64x64 tile, 256 threads.
// mode 0: out-proj (A := g_X, row-major out)
// mode 1: q-proj   (scale + scatter to g_Qp (bh,q,d))
// mode 2: kv-proj  (K -> g_Kt transposed scatter, V -> g_V row-major float4)
// ---------------------------------------------------------------------------
__global__ void __launch_bounds__(256) gemm_kernel(
    const float* __restrict__ A, const float* __restrict__ W,
    const float* __restrict__ bias, float* __restrict__ out,
    int M, int N, int K, int mode)
{
    __shared__ float As[64*32];
    __shared__ float Ws[64*33];

    if (mode == 0) A = g_X;

    const int tid = threadIdx.x;
    const int ty = tid >> 4, tx = tid & 15;
    const int m0 = blockIdx.x * 64, n0 = blockIdx.y * 64;

    float s[4][4] = {};

    for (int kc = 0; kc < K; kc += 32) {
        {
            int f = tid * 8, r = f >> 5, k = f & 31;
            const float4* src = (const float4*)&A[(size_t)(m0 + r) * K + kc + k];
            *(float4*)&As[r*32 + k]     = src[0];
            *(float4*)&As[r*32 + k + 4] = src[1];
        }
        {
            int f = tid * 8, c = f >> 5, k = f & 31;
            const float4* src = (const float4*)&W[(size_t)(n0 + c) * K + kc + k];
            float4 v0 = src[0], v1 = src[1];
            float* d = &Ws[c*33 + k];
            d[0]=v0.x; d[1]=v0.y; d[2]=v0.z; d[3]=v0.w;
            d[4]=v1.x; d[5]=v1.y; d[6]=v1.z; d[7]=v1.w;
        }
        __syncthreads();

        #pragma unroll
        for (int k = 0; k < 32; k += 4) {
            float4 a[4];
            #pragma unroll
            for (int i = 0; i < 4; i++) a[i] = *(float4*)&As[(ty*4+i)*32 + k];
            #pragma unroll
            for (int j = 0; j < 4; j++) {
                const float* wp = &Ws[(tx*4+j)*33 + k];
                float w0 = wp[0], w1 = wp[1], w2 = wp[2], w3 = wp[3];
                #pragma unroll
                for (int i = 0; i < 4; i++)
                    s[i][j] += a[i].x*w0 + a[i].y*w1 + a[i].z*w2 + a[i].w*w3;
            }
        }
        __syncthreads();
    }

    const int cbase = n0 + tx*4;

    if (mode == 0) {
        float4 bb = *(const float4*)&bias[cbase];
        #pragma unroll
        for (int i = 0; i < 4; i++) {
            int m = m0 + ty*4 + i;
            *(float4*)&out[(size_t)m * N + cbase] =
                make_float4(s[i][0]+bb.x, s[i][1]+bb.y, s[i][2]+bb.z, s[i][3]+bb.w);
        }
    } else if (mode == 1) {
        float4 bb = *(const float4*)&bias[cbase];
        int h = cbase >> 5, d = cbase & 31;
        #pragma unroll
        for (int i = 0; i < 4; i++) {
            int m = m0 + ty*4 + i;
            int b = m >> 10, qi = m & 1023;
            *(float4*)&g_Qp[(size_t)((b*NH + h)*QL + qi)*HD + d] =
                make_float4((s[i][0]+bb.x)*QSCALE, (s[i][1]+bb.y)*QSCALE,
                            (s[i][2]+bb.z)*QSCALE, (s[i][3]+bb.w)*QSCALE);
        }
    } else {
        int sel = cbase >> 8;                   // uniform per block (n0 mult of 64)
        if (sel) {                              // V: (bh, k, d) float4 stores
            int h = (cbase >> 5) & 7, d = cbase & 31;
            float4 bb = *(const float4*)&bias[cbase];
            #pragma unroll
            for (int i = 0; i < 4; i++) {
                int m = m0 + ty*4 + i;
                int b = m >> 12, kk = m & 4095;
                *(float4*)&g_V[((size_t)(b*NH + h)*KVL + kk)*HD + d] =
                    make_float4(s[i][0]+bb.x, s[i][1]+bb.y, s[i][2]+bb.z, s[i][3]+bb.w);
            }
        } else {                                // K: (bh, d, k) transposed scatter
            #pragma unroll
            for (int j = 0; j < 4; j++) {
                int c = cbase + j;
                int h = (c >> 5) & 7, d = c & 31;
                float bv = bias[c];
                #pragma unroll
                for (int i = 0; i < 4; i++) {
                    int m = m0 + ty*4 + i;
                    int b = m >> 12, kk = m & 4095;
                    g_Kt[((size_t)(b*NH + h)*HD + d)*KVL + kk] = s[i][j] + bv;
                }
            }
        }
    }
}

// ---------------------------------------------------------------------------
// Fused attention. One CTA per (bh, 64-q-row tile). Online softmax.
// Analytic bias index (exact replication of the reference reshape):
//   row q, col = kt*64 + d :
//     c = kt & 31 (wz), p = kt >> 5 (hx parity)
//     zf = 528 + (q>>5)*32 + c ; zh = zf>>6 ; zw = zf&63
//     t = p*32 + d ; xh = (q&31) + (t>>6) ; xw = t&63
//     idx = (zh-xh+63)*127 + (zw-xw+63)
//   and for a thread's 4 consecutive cols: idx(j) = idx(0) - j.
// ---------------------------------------------------------------------------
__device__ __forceinline__ void cpa16(uint32_t dst, const float* src)
{
    asm volatile("cp.async.ca.shared.global [%0], [%1], 16;\n" :: "r"(dst), "l"(src));
}

#define SM_Q    0
#define SM_K    2048
#define SM_V    6144
#define SM_P    10752
#define SM_AL   14848
#define SM_LL   14912
#define SM_FLOATS 14976

__global__ void __launch_bounds__(256) attn_kernel()
{
    extern __shared__ float sm[];
    float* Qs  = sm + SM_Q;
    float* Kts = sm + SM_K;     // 2 x [32][64]
    float* Vkd = sm + SM_V;     // 2 x [64][36]
    float* Ps  = sm + SM_P;     // [64][64]
    float* Al  = sm + SM_AL;
    float* Ll  = sm + SM_LL;

    const int tid  = threadIdx.x;
    const int ty   = tid >> 4, tx = tid & 15;
    const int lane = tid & 31, w  = tid >> 5;
    const int bh   = blockIdx.y, b = bh >> 3, h = bh & 7;
    const int qt   = blockIdx.x;

    const uint32_t smbase = (uint32_t)__cvta_generic_to_shared(sm);

    // Q tile (read once, broadcast-consumed)
    {
        const float4* src = (const float4*)&g_Qp[((size_t)bh*QL + qt*64)*HD + tid*8];
        *(float4*)&Qs[tid*8]     = src[0];
        *(float4*)&Qs[tid*8 + 4] = src[1];
    }

    const float* bT = &g_biasT[h * NT];
    const size_t kbase = (size_t)bh * HD * KVL;
    const size_t vbase = (size_t)bh * KVL * HD;

    const int fk = tid*8, kd = fk >> 6, kj = fk & 63;
    const int vk = fk >> 5, vd = fk & 31;

    // preload tile 0
    {
        const float* ks = &g_Kt[kbase + (size_t)kd*KVL + kj];
        uint32_t kdst = smbase + (SM_K + kd*64 + kj)*4;
        cpa16(kdst, ks); cpa16(kdst+16, ks+4);
        const float* vs = &g_V[vbase + (size_t)vk*HD + vd];
        uint32_t vdst = smbase + (SM_V + vk*36 + vd)*4;
        cpa16(vdst, vs); cpa16(vdst+16, vs+4);
        asm volatile("cp.async.commit_group;\n");
    }

    float m[4], l[4], O[8];
    #pragma unroll
    for (int i = 0; i < 4; i++) { m[i] = -CUDART_INF_F; l[i] = 0.f; }
    #pragma unroll
    for (int r = 0; r < 8; r++) O[r] = 0.f;

    // per-row bias seed components (q rows this thread owns: qt*64+ty*4+i)
    //   zf_base(i) = 528 + (q>>5)*32   (c added per tile)
    //   xh_base(i) = q & 31
    int zfb[4], xhb[4];
    #pragma unroll
    for (int i = 0; i < 4; i++) {
        int q = qt*64 + ty*4 + i;
        zfb[i] = 528 + (q >> 5) * 32;
        xhb[i] = q & 31;
    }

    for (int kt = 0; kt < KVL/64; kt++) {
        const int buf = kt & 1;

        // ---- bias-initialized accumulators (LDGs issued before barrier) ----
        const int c = kt & 31, p = kt >> 5;
        const int t0 = p*32 + tx*4;
        const int tcar = t0 >> 6, xw0 = t0 & 63;
        float s[4][4];
        #pragma unroll
        for (int i = 0; i < 4; i++) {
            int zf = zfb[i] + c;
            int zh = zf >> 6, zw = zf & 63;
            int xh = xhb[i] + tcar;
            int idx0 = (zh - xh + 63)*127 + (zw - xw0 + 63);
            s[i][0] = __ldg(&bT[idx0    ]);
            s[i][1] = __ldg(&bT[idx0 - 1]);
            s[i][2] = __ldg(&bT[idx0 - 2]);
            s[i][3] = __ldg(&bT[idx0 - 3]);
        }

        asm volatile("cp.async.wait_group 0;\n");
        __syncthreads();   // tile visible; prev iter's PV done with other buffer

        if (kt < KVL/64 - 1) {   // prefetch next tile into other buffer
            const int nb = (kt+1) & 1;
            const int kbn = (kt+1)*64;
            const float* ks = &g_Kt[kbase + (size_t)kd*KVL + kbn + kj];
            uint32_t kdst = smbase + (SM_K + nb*2048 + kd*64 + kj)*4;
            cpa16(kdst, ks); cpa16(kdst+16, ks+4);
            const float* vs = &g_V[vbase + (size_t)(kbn + vk)*HD + vd];
            uint32_t vdst = smbase + (SM_V + nb*2304 + vk*36 + vd)*4;
            cpa16(vdst, vs); cpa16(vdst+16, vs+4);
            asm volatile("cp.async.commit_group;\n");
        }

        const float* K = &Kts[buf*2048];
        const float* V = &Vkd[buf*2304];

        // ---- S = QK^T + bias ----
        #pragma unroll
        for (int d4 = 0; d4 < 32; d4 += 4) {
            float4 k0 = *(const float4*)&K[(d4+0)*64 + tx*4];
            float4 k1 = *(const float4*)&K[(d4+1)*64 + tx*4];
            float4 k2 = *(const float4*)&K[(d4+2)*64 + tx*4];
            float4 k3 = *(const float4*)&K[(d4+3)*64 + tx*4];
            #pragma unroll
            for (int i = 0; i < 4; i++) {
                float4 q = *(const float4*)&Qs[(ty*4+i)*32 + d4];
                s[i][0] += q.x*k0.x + q.y*k1.x + q.z*k2.x + q.w*k3.x;
                s[i][1] += q.x*k0.y + q.y*k1.y + q.z*k2.y + q.w*k3.y;
                s[i][2] += q.x*k0.z + q.y*k1.z + q.z*k2.z + q.w*k3.z;
                s[i][3] += q.x*k0.w + q.y*k1.w + q.z*k2.w + q.w*k3.w;
            }
        }

        // ---- online softmax (warp-private rows) ----
        #pragma unroll
        for (int i = 0; i < 4; i++) {
            float mt = fmaxf(fmaxf(s[i][0], s[i][1]), fmaxf(s[i][2], s[i][3]));
            #pragma unroll
            for (int o = 8; o >= 1; o >>= 1)
                mt = fmaxf(mt, __shfl_xor_sync(0xffffffffu, mt, o));
            float mn    = fmaxf(m[i], mt);
            float alpha = __expf(m[i] - mn);
            m[i] = mn;
            float p0 = __expf(s[i][0]-mn), p1 = __expf(s[i][1]-mn);
            float p2 = __expf(s[i][2]-mn), p3 = __expf(s[i][3]-mn);
            float rs = p0 + p1 + p2 + p3;
            #pragma unroll
            for (int o = 8; o >= 1; o >>= 1)
                rs += __shfl_xor_sync(0xffffffffu, rs, o);
            l[i] = l[i]*alpha + rs;
            if (tx == 0) Al[ty*4 + i] = alpha;
            *(float4*)&Ps[(ty*4+i)*64 + tx*4] = make_float4(p0, p1, p2, p3);
        }
        __syncwarp();   // Ps/Al are warp-private

        // ---- O += P V : lane = d, warp owns its 8 rows ----
        float av[8];
        #pragma unroll
        for (int r = 0; r < 8; r++) av[r] = Al[w*8 + r];
        #pragma unroll
        for (int r = 0; r < 8; r++) O[r] *= av[r];

        #pragma unroll 4
        for (int k4 = 0; k4 < 64; k4 += 4) {
            float vx = V[(k4+0)*36 + lane];
            float vy = V[(k4+1)*36 + lane];
            float vz = V[(k4+2)*36 + lane];
            float vw = V[(k4+3)*36 + lane];
            #pragma unroll
            for (int r = 0; r < 8; r++) {
                float4 pr = *(const float4*)&Ps[(w*8+r)*64 + k4];
                O[r] += pr.x*vx + pr.y*vy + pr.z*vz + pr.w*vw;
            }
        }
    }

    // epilogue
    if (tx == 0) {
        #pragma unroll
        for (int i = 0; i < 4; i++) Ll[ty*4 + i] = l[i];
    }
    __syncwarp();
    #pragma unroll
    for (int r = 0; r < 8; r++) {
        int row = w*8 + r;
        float inv = 1.0f / Ll[row];
        int q = qt*64 + row;
        g_X[((size_t)b*QL + q)*CC + h*HD + lane] = O[r] * inv;
    }
}

// ---------------------------------------------------------------------------
extern "C" void kernel_launch(void* const* d_in, const int* in_sizes, int n_in,
                              void* d_out, int out_size)
{
    const float* q          = (const float*)d_in[0];
    const float* kv         = (const float*)d_in[1];
    const float* Wq         = (const float*)d_in[2];
    const float* bq         = (const float*)d_in[3];
    const float* Wkv        = (const float*)d_in[4];
    const float* bkv        = (const float*)d_in[5];
    const float* bias_table = (const float*)d_in[6];
    const float* Wp         = (const float*)d_in[7];
    const float* bp         = (const float*)d_in[8];
    float* out = (float*)d_out;

    cudaFuncSetAttribute(attn_kernel,
        cudaFuncAttributeMaxDynamicSharedMemorySize, SM_FLOATS * 4);

    dim3 blk(256);
    bias_prep<<<(NH*NT + 255)/256, blk>>>(bias_table);
    gemm_kernel<<<dim3(64, 4),  blk>>>(q,  Wq,  bq,  nullptr, BB*QL,  CC,   CC, 1);
    gemm_kernel<<<dim3(256, 8), blk>>>(kv, Wkv, bkv, nullptr, BB*KVL, 2*CC, CC, 2);
    attn_kernel<<<dim3(QL/64, BB*NH), blk, SM_FLOATS * 4>>>();
    gemm_kernel<<<dim3(64, 4),  blk>>>(nullptr, Wp, bp, out, BB*QL, CC, CC, 0);
}